// round 2
// baseline (speedup 1.0000x reference)
#include <cuda_runtime.h>

#define HDIM 100
#define G4   400
#define TSEQ 8192
#define FUT  1024
#define TOTSTEPS (TSEQ + FUT)
#define NS   8          // h1 ring slots (power of 2)
#define NTHR 800

// ---------------- global communication scratch (device globals; no allocs) ----------------
__device__ float g_h1buf[NS][HDIM];
__device__ int   g_fh1[NS];
__device__ float g_h2a[4][50];
__device__ float g_h2b[4][50];
__device__ int   g_fh2a[4];
__device__ int   g_fh2b[4];
__device__ float g_yv;
__device__ int   g_fy;
__device__ int   g_ack1;
__device__ int   g_ack2;

__device__ __forceinline__ int ld_acq(const int* p) {
    int v;
    asm volatile("ld.acquire.gpu.b32 %0, [%1];" : "=r"(v) : "l"(p) : "memory");
    return v;
}
__device__ __forceinline__ void st_rel(int* p, int v) {
    asm volatile("st.release.gpu.b32 [%0], %1;" :: "l"(p), "r"(v) : "memory");
}
__device__ __forceinline__ float sigm(float x) { return 1.0f / (1.0f + expf(-x)); }

__global__ void init_flags_kernel() {
    int i = threadIdx.x;
    if (i < NS) g_fh1[i] = 0;
    if (i < 4) { g_fh2a[i] = 0; g_fh2b[i] = 0; }
    if (i == 0) { g_fy = 0; g_ack1 = 0; g_ack2 = 0; }
}

// Persistent 3-CTA kernel:
//  CTA0: layer-1 LSTM (weights in registers: 2 rows x 25 cols per thread)
//  CTA1: layer-2 LSTM, hidden units 0..49   (rows x [h1|h2] cols in registers)
//  CTA2: layer-2 LSTM, hidden units 50..99
// Cross-CTA h-vector exchange via L2 with acquire/release flags.
__global__ void __launch_bounds__(NTHR, 1) lstm_decoder_kernel(
    const float* __restrict__ input,
    const float* __restrict__ enc_h,
    const float* __restrict__ enc_c,
    const float* __restrict__ w_ih1,
    const float* __restrict__ w_hh1,
    const float* __restrict__ b_ih1,
    const float* __restrict__ b_hh1,
    const float* __restrict__ w_ih2,
    const float* __restrict__ w_hh2,
    const float* __restrict__ b_ih2,
    const float* __restrict__ b_hh2,
    const float* __restrict__ w_lin,
    const float* __restrict__ b_lin,
    float* __restrict__ out)
{
    __shared__ float sx[TSEQ];     // CTA0: staged input sequence (32 KB)
    __shared__ float sin_[256];    // CTA0: h1[100] ; CTA1/2: [h1(0..99) | h2(100..199)]
    __shared__ float sg[G4];       // gate pre-activations
    __shared__ float swl[128];     // w_lin staged (CTA1)
    __shared__ float sbc[1];       // broadcast slot (future-phase x for CTA0)

    const int t   = threadIdx.x;
    const int cta = blockIdx.x;

    if (cta == 0) {
        // ---------------- layer 1 ----------------
        // thread -> (slot, q): rows r0=slot, r1=slot+200; cols q*25..q*25+24
        const int slot = t >> 2;
        const int q    = t & 3;
        const int r0 = slot, r1 = slot + 200;

        float w0[25], w1[25];
#pragma unroll
        for (int j = 0; j < 25; j++) {
            int c = q * 25 + j;
            w0[j] = w_hh1[r0 * HDIM + c];
            w1[j] = w_hh1[r1 * HDIM + c];
        }
        const float wi0 = w_ih1[r0], wi1 = w_ih1[r1];
        const float bb0 = b_ih1[r0] + b_hh1[r0];
        const float bb1 = b_ih1[r1] + b_hh1[r1];

        for (int i = t; i < TSEQ; i += NTHR) sx[i] = input[i];
        float c1 = 0.0f;
        if (t < HDIM) { sin_[t] = enc_h[t]; c1 = enc_c[t]; }
        __syncthreads();

        for (int step = 0; step < TOTSTEPS; ++step) {
            if (t == 0) {
                if (step >= NS) {                 // ring backpressure
                    int need = step - NS + 1;
                    while (ld_acq(&g_ack1) < need) {}
                    while (ld_acq(&g_ack2) < need) {}
                }
                if (step >= TSEQ) {               // autoregressive feedback
                    while (ld_acq(&g_fy) < step) {}
                    sbc[0] = g_yv;
                }
            }
            __syncthreads();
            const float x = (step < TSEQ) ? sx[step] : sbc[0];

            float a0 = 0.0f, a1 = 0.0f;
#pragma unroll
            for (int j = 0; j < 25; j++) {
                float hv = sin_[q * 25 + j];
                a0 = fmaf(w0[j], hv, a0);
                a1 = fmaf(w1[j], hv, a1);
            }
            a0 += __shfl_xor_sync(0xffffffffu, a0, 1);
            a0 += __shfl_xor_sync(0xffffffffu, a0, 2);
            a1 += __shfl_xor_sync(0xffffffffu, a1, 1);
            a1 += __shfl_xor_sync(0xffffffffu, a1, 2);
            if (q == 0) {
                sg[r0] = a0 + bb0 + x * wi0;
                sg[r1] = a1 + bb1 + x * wi1;
            }
            __syncthreads();

            if (t < HDIM) {
                float ig = sg[t], fg = sg[t + HDIM], gg = sg[t + 2 * HDIM], og = sg[t + 3 * HDIM];
                c1 = sigm(fg) * c1 + sigm(ig) * tanhf(gg);
                float hh = sigm(og) * tanhf(c1);
                sin_[t] = hh;
                g_h1buf[step & (NS - 1)][t] = hh;
                __threadfence();
            }
            __syncthreads();
            if (t == 0) st_rel(&g_fh1[step & (NS - 1)], step + 1);
        }
    } else {
        // ---------------- layer 2 (half of hidden units per CTA) ----------------
        const int U0 = (cta == 1) ? 0 : 50;
        const int U1 = 50 - U0;
        // thread -> (rr, q): local rows lr0=rr, lr1=rr+100; cols q*25..q*25+24 of [h1|h2]
        const int rr = t >> 3;
        const int q  = t & 7;
        const int lr0 = rr, lr1 = rr + 100;
        const int R0 = (lr0 / 50) * HDIM + U0 + (lr0 % 50);
        const int R1 = (lr1 / 50) * HDIM + U0 + (lr1 % 50);

        float w0[25], w1[25];
#pragma unroll
        for (int j = 0; j < 25; j++) {
            int c = q * 25 + j;
            w0[j] = (c < HDIM) ? w_ih2[R0 * HDIM + c] : w_hh2[R0 * HDIM + (c - HDIM)];
            w1[j] = (c < HDIM) ? w_ih2[R1 * HDIM + c] : w_hh2[R1 * HDIM + (c - HDIM)];
        }
        const float bb0 = b_ih2[R0] + b_hh2[R0];
        const float bb1 = b_ih2[R1] + b_hh2[R1];

        if (t < HDIM) { swl[t] = w_lin[t]; sin_[HDIM + t] = 0.0f; }
        float c2 = 0.0f;
        const float blin = b_lin[0];
        __syncthreads();

        for (int step = 0; step < TOTSTEPS; ++step) {
            // 1. wait for h1(step) from CTA0
            if (t == 0) { while (ld_acq(&g_fh1[step & (NS - 1)]) < step + 1) {} }
            __syncthreads();
            if (t < HDIM) sin_[t] = g_h1buf[step & (NS - 1)][t];
            __syncthreads();
            if (t == 0) st_rel((cta == 1) ? &g_ack1 : &g_ack2, step + 1);

            // 2. matvec over [h1(step) | h2(step-1)]
            float a0 = 0.0f, a1 = 0.0f;
#pragma unroll
            for (int j = 0; j < 25; j++) {
                float hv = sin_[q * 25 + j];
                a0 = fmaf(w0[j], hv, a0);
                a1 = fmaf(w1[j], hv, a1);
            }
            a0 += __shfl_xor_sync(0xffffffffu, a0, 1);
            a0 += __shfl_xor_sync(0xffffffffu, a0, 2);
            a0 += __shfl_xor_sync(0xffffffffu, a0, 4);
            a1 += __shfl_xor_sync(0xffffffffu, a1, 1);
            a1 += __shfl_xor_sync(0xffffffffu, a1, 2);
            a1 += __shfl_xor_sync(0xffffffffu, a1, 4);
            if (q == 0) { sg[lr0] = a0 + bb0; sg[lr1] = a1 + bb1; }
            __syncthreads();

            // 3. activations for this CTA's 50 units; publish own h2 half
            if (t < 50) {
                float ig = sg[t], fg = sg[t + 50], gg = sg[t + 100], og = sg[t + 150];
                c2 = sigm(fg) * c2 + sigm(ig) * tanhf(gg);
                float hh = sigm(og) * tanhf(c2);
                sin_[HDIM + U0 + t] = hh;
                if (cta == 1) g_h2a[step & 3][t] = hh;
                else          g_h2b[step & 3][t] = hh;
                __threadfence();
            }
            __syncthreads();
            if (t == 0) {
                st_rel((cta == 1) ? &g_fh2a[step & 3] : &g_fh2b[step & 3], step + 1);
                int* of = (cta == 1) ? &g_fh2b[step & 3] : &g_fh2a[step & 3];
                while (ld_acq(of) < step + 1) {}
            }
            __syncthreads();
            if (t < 50) {
                const float* oth = (cta == 1) ? g_h2b[step & 3] : g_h2a[step & 3];
                sin_[HDIM + U1 + t] = oth[t];
            }
            __syncthreads();

            // 4. CTA1 computes y = w_lin . h2 + b_lin, writes output, feeds back in future phase
            if (cta == 1 && t < 32) {
                float p = 0.0f;
                for (int u = t; u < HDIM; u += 32) p = fmaf(swl[u], sin_[HDIM + u], p);
                p += __shfl_xor_sync(0xffffffffu, p, 16);
                p += __shfl_xor_sync(0xffffffffu, p, 8);
                p += __shfl_xor_sync(0xffffffffu, p, 4);
                p += __shfl_xor_sync(0xffffffffu, p, 2);
                p += __shfl_xor_sync(0xffffffffu, p, 1);
                if (t == 0) {
                    float y = p + blin;
                    out[step] = y;
                    if (step >= TSEQ - 1) {
                        g_yv = y;
                        st_rel(&g_fy, step + 1);
                    }
                }
            }
        }
    }
}

extern "C" void kernel_launch(void* const* d_in, const int* in_sizes, int n_in,
                              void* d_out, int out_size) {
    (void)in_sizes; (void)n_in; (void)out_size;
    const float* input = (const float*)d_in[0];
    const float* eh    = (const float*)d_in[1];
    const float* ec    = (const float*)d_in[2];
    const float* wih1  = (const float*)d_in[3];
    const float* whh1  = (const float*)d_in[4];
    const float* bih1  = (const float*)d_in[5];
    const float* bhh1  = (const float*)d_in[6];
    const float* wih2  = (const float*)d_in[7];
    const float* whh2  = (const float*)d_in[8];
    const float* bih2  = (const float*)d_in[9];
    const float* bhh2  = (const float*)d_in[10];
    const float* wlin  = (const float*)d_in[11];
    const float* blin  = (const float*)d_in[12];
    float* out = (float*)d_out;

    init_flags_kernel<<<1, 32>>>();
    lstm_decoder_kernel<<<3, NTHR>>>(input, eh, ec, wih1, whh1, bih1, bhh1,
                                     wih2, whh2, bih2, bhh2, wlin, blin, out);
}

// round 4
// speedup vs baseline: 1.5586x; 1.5586x over previous
#include <cuda_runtime.h>

#define H     100
#define G4    400
#define TSEQ  8192
#define FUT   1024
#define TOT   (TSEQ + FUT)
#define NSLOT 16
#define NTHR  448

// ---------------- global communication scratch ----------------
__device__ __align__(16) float g_h1buf[NSLOT][128];   // CTA0 -> CTA1 (h1 ring)
__device__ __align__(16) float g_pbuf [NSLOT][400];   // CTA1 -> CTA2 (p ring)
__device__ float g_y1;                                // CTA2 -> CTA0 feedback
__device__ int   g_ch1, g_cp, g_cy, g_ack1, g_ack2;

static __device__ __forceinline__ int ld_acq(const int* p) {
    int v; asm volatile("ld.acquire.gpu.b32 %0, [%1];" : "=r"(v) : "l"(p) : "memory"); return v;
}
static __device__ __forceinline__ void st_rel(int* p, int v) {
    asm volatile("st.release.gpu.b32 [%0], %1;" :: "l"(p), "r"(v) : "memory");
}
static __device__ __forceinline__ float ldg_coh(const float* p) {
    float v; asm volatile("ld.relaxed.gpu.b32 %0, [%1];" : "=f"(v) : "l"(p) : "memory"); return v;
}
static __device__ __forceinline__ float4 ldg4_coh(const float4* p) {
    float4 v;
    asm volatile("ld.relaxed.gpu.v4.f32 {%0,%1,%2,%3}, [%4];"
                 : "=f"(v.x), "=f"(v.y), "=f"(v.z), "=f"(v.w) : "l"(p) : "memory");
    return v;
}
static __device__ __forceinline__ void fence_gpu() {
    asm volatile("fence.acq_rel.gpu;" ::: "memory");
}
static __device__ __forceinline__ void ffma2(unsigned long long& a, unsigned long long w, unsigned long long h) {
    asm("fma.rn.f32x2 %0, %1, %2, %3;" : "=l"(a) : "l"(w), "l"(h), "l"(a));
}
static __device__ __forceinline__ float f2lo(unsigned long long a) { return __uint_as_float((unsigned)a); }
static __device__ __forceinline__ float f2hi(unsigned long long a) { return __uint_as_float((unsigned)(a >> 32)); }
static __device__ __forceinline__ float sigm(float x)  { return __fdividef(1.0f, 1.0f + __expf(-x)); }
static __device__ __forceinline__ float tanh_(float x) { return __fdividef(2.0f, 1.0f + __expf(-2.0f * x)) - 1.0f; }

// 100-element dot: 50 packed f32x2 FMAs against register-resident weights.
static __device__ __forceinline__ float dot100(const unsigned long long* W, const float* sh) {
    const unsigned long long* h = (const unsigned long long*)sh;
    unsigned long long a0 = 0ull, a1 = 0ull;
#pragma unroll
    for (int j = 0; j < 50; j += 2) { ffma2(a0, W[j], h[j]); ffma2(a1, W[j + 1], h[j + 1]); }
    return f2lo(a0) + f2hi(a0) + f2lo(a1) + f2hi(a1);
}

__global__ void init_flags_kernel() {
    if (threadIdx.x == 0) { g_ch1 = 0; g_cp = 0; g_cy = 0; g_ack1 = 0; g_ack2 = 0; }
}

// CTA0: layer-1 LSTM (h1 recurrence local).  CTA1: p = W_ih2@h1 + b2 (feed-forward).
// CTA2: q = W_hh2@h2 (local recurrence) + p -> gates -> h2 -> y.
// Seq phase: lookahead prefetch pipeline.  Future phase: blocking current-step loads (DAG, no deadlock).
__global__ void __launch_bounds__(NTHR, 1) lstm_decoder_kernel(
    const float* __restrict__ input,
    const float* __restrict__ enc_h,
    const float* __restrict__ enc_c,
    const float* __restrict__ w_ih1,
    const float* __restrict__ w_hh1,
    const float* __restrict__ b_ih1,
    const float* __restrict__ b_hh1,
    const float* __restrict__ w_ih2,
    const float* __restrict__ w_hh2,
    const float* __restrict__ b_ih2,
    const float* __restrict__ b_hh2,
    const float* __restrict__ w_lin,
    const float* __restrict__ b_lin,
    float* __restrict__ out)
{
    __shared__ __align__(16) float sx[TSEQ];     // CTA0 only
    __shared__ __align__(16) float shA[2][128];  // CTA0: [0]=h1 ; CTA1: h1 dbuf ; CTA2: [0]=h2
    __shared__ __align__(16) float spx[2][400];  // CTA2: p double-buf
    __shared__ float sg[400];
    __shared__ float swl[112];
    __shared__ float syp[2][112];
    __shared__ float sxb[1];

    const int t   = threadIdx.x;
    const int cta = blockIdx.x;

    if (cta == 0) {
        // ======================= layer 1 =======================
        unsigned long long Wr[50];
        float wi = 0.f, bb = 0.f, c1 = 0.f;
        if (t < G4) {
            const unsigned long long* wr = (const unsigned long long*)(w_hh1 + t * H);
#pragma unroll
            for (int j = 0; j < 50; j++) Wr[j] = wr[j];
            wi = w_ih1[t];
            bb = b_ih1[t] + b_hh1[t];
        }
        for (int i = t; i < TSEQ; i += NTHR) sx[i] = input[i];
        if (t < H) { shA[0][t] = enc_h[t]; c1 = enc_c[t]; }
        __syncthreads();

        for (int step = 0; step < TOT; ++step) {
            // ---- top (polls, off the matvec path) ----
            if (t == 400) {                       // ring backpressure, every 8 steps
                if ((step & 7) == 0 && step >= NSLOT) {
                    while (ld_acq(&g_ack1) < step - 8) {}
                }
            } else if (t == 401) {                // autoregressive feedback (future)
                if (step >= TSEQ) {
                    while (ld_acq(&g_cy) < step) {}
                    sxb[0] = ldg_coh(&g_y1);
                }
            }
            if (step >= TSEQ) __syncthreads();    // Bf: order sxb before consumption

            float a = 0.f;
            if (t < G4) a = dot100(Wr, shA[0]);
            if (t < G4) {
                float x = (step < TSEQ) ? sx[step] : sxb[0];
                sg[t] = fmaf(x, wi, a + bb);
            }
            __syncthreads();                      // B1
            if (t < H) {
                float ig = sg[t], fg = sg[t + 100], gg = sg[t + 200], og = sg[t + 300];
                c1 = sigm(fg) * c1 + sigm(ig) * tanh_(gg);
                float hh = sigm(og) * tanh_(c1);
                shA[0][t] = hh;
                g_h1buf[step & (NSLOT - 1)][t] = hh;
            }
            __syncthreads();                      // B2
            if (t == 416) { fence_gpu(); st_rel(&g_ch1, step + 1); }
        }
    } else if (cta == 1) {
        // ======================= p = W_ih2 @ h1 + b2 =======================
        unsigned long long Wr[50];
        float bb = 0.f;
        if (t < G4) {
            const unsigned long long* wr = (const unsigned long long*)(w_ih2 + t * H);
#pragma unroll
            for (int j = 0; j < 50; j++) Wr[j] = wr[j];
            bb = b_ih2[t] + b_hh2[t];
        }
        if (t >= 416) {                           // prologue: load h1(0)
            if (t == 416) { while (ld_acq(&g_ch1) < 1) {} }
            __syncwarp();
            int l = t - 416;
            if (l < 25) ((float4*)shA[0])[l] = ldg4_coh((const float4*)g_h1buf[0] + l);
        }
        __syncthreads();

        for (int step = 0; step < TOT; ++step) {
            // ---- top ----
            if (t >= 416) {
                if (step + 1 < TSEQ) {            // seq: prefetch h1(step+1)
                    if (t == 416) { while (ld_acq(&g_ch1) < step + 2) {} }
                    __syncwarp();
                    int l = t - 416, s = (step + 1) & (NSLOT - 1), b = (step + 1) & 1;
                    if (l < 25) ((float4*)shA[b])[l] = ldg4_coh((const float4*)g_h1buf[s] + l);
                } else if (step >= TSEQ) {        // future: blocking current load
                    if (t == 416) { while (ld_acq(&g_ch1) < step + 1) {} }
                    __syncwarp();
                    int l = t - 416, s = step & (NSLOT - 1), b = step & 1;
                    if (l < 25) ((float4*)shA[b])[l] = ldg4_coh((const float4*)g_h1buf[s] + l);
                }
            } else if (t == 400) {                // p-ring backpressure
                if ((step & 7) == 0 && step >= NSLOT) {
                    while (ld_acq(&g_ack2) < step - 8) {}
                }
            }
            if (step >= TSEQ) __syncthreads();    // Bf: order blocking load before matvec

            if (t < G4) {
                float a = dot100(Wr, shA[step & 1]);
                g_pbuf[step & (NSLOT - 1)][t] = a + bb;
            }
            __syncthreads();                      // B1
            if (t == 416) {
                fence_gpu();
                st_rel(&g_cp, step + 1);
                st_rel(&g_ack1, step + 1);        // h1(<=step) consumed
            }
        }
    } else {
        // ======================= layer-2 recurrence + output =======================
        unsigned long long Wr[50];
        float c2 = 0.f;
        if (t < G4) {
            const unsigned long long* wr = (const unsigned long long*)(w_hh2 + t * H);
#pragma unroll
            for (int j = 0; j < 50; j++) Wr[j] = wr[j];
        }
        if (t < H) { shA[0][t] = 0.f; swl[t] = w_lin[t]; }
        const float blin = b_lin[0];
        if (t >= 416) {                           // prologue: load p(0)
            if (t == 416) { while (ld_acq(&g_cp) < 1) {} }
            __syncwarp();
            int l = t - 416;
            for (int k = l; k < 100; k += 32)
                ((float4*)spx[0])[k] = ldg4_coh((const float4*)g_pbuf[0] + k);
        }
        __syncthreads();

        for (int step = 0; step < TOT; ++step) {
            // ---- top ----
            if (t >= 416) {
                if (step + 1 < TSEQ) {            // seq: prefetch p(step+1)
                    if (t == 416) { while (ld_acq(&g_cp) < step + 2) {} }
                    __syncwarp();
                    int l = t - 416, s = (step + 1) & (NSLOT - 1), b = (step + 1) & 1;
                    for (int k = l; k < 100; k += 32)
                        ((float4*)spx[b])[k] = ldg4_coh((const float4*)g_pbuf[s] + k);
                } else if (step >= TSEQ) {        // future: blocking current load
                    if (t == 416) { while (ld_acq(&g_cp) < step + 1) {} }
                    __syncwarp();
                    int l = t - 416, s = step & (NSLOT - 1), b = step & 1;
                    for (int k = l; k < 100; k += 32)
                        ((float4*)spx[b])[k] = ldg4_coh((const float4*)g_pbuf[s] + k);
                }
                // delayed y(step-1) — off the critical path (seq region)
                int ys = step - 1;
                if (ys >= 0 && ys < TSEQ - 1) {
                    int l = t - 416; float v = 0.f;
                    if (l < 25) {
                        const float* sp = syp[ys & 1]; int b4 = 4 * l;
                        v = sp[b4] + sp[b4 + 1] + sp[b4 + 2] + sp[b4 + 3];
                    }
                    v += __shfl_xor_sync(0xffffffffu, v, 16);
                    v += __shfl_xor_sync(0xffffffffu, v, 8);
                    v += __shfl_xor_sync(0xffffffffu, v, 4);
                    v += __shfl_xor_sync(0xffffffffu, v, 2);
                    v += __shfl_xor_sync(0xffffffffu, v, 1);
                    if (l == 0) out[ys] = v + blin;
                }
            }
            if (step >= TSEQ) __syncthreads();    // Bf: order blocking load before sg combine

            if (t < G4) {
                float a = dot100(Wr, shA[0]);     // q = W_hh2 @ h2(step-1)
                sg[t] = a + spx[step & 1][t];
            }
            __syncthreads();                      // B1
            if (t < H) {
                float ig = sg[t], fg = sg[t + 100], gg = sg[t + 200], og = sg[t + 300];
                c2 = sigm(fg) * c2 + sigm(ig) * tanh_(gg);
                float hh = sigm(og) * tanh_(c2);
                shA[0][t] = hh;
                syp[step & 1][t] = hh * swl[t];
            }
            __syncthreads();                      // B2
            if (t == 400) { fence_gpu(); st_rel(&g_ack2, step + 1); }  // p(<=step) consumed
            if (t >= 416 && step >= TSEQ - 1) {   // inline y (feedback path)
                int l = t - 416; float v = 0.f;
                if (l < 25) {
                    const float* sp = syp[step & 1]; int b4 = 4 * l;
                    v = sp[b4] + sp[b4 + 1] + sp[b4 + 2] + sp[b4 + 3];
                }
                v += __shfl_xor_sync(0xffffffffu, v, 16);
                v += __shfl_xor_sync(0xffffffffu, v, 8);
                v += __shfl_xor_sync(0xffffffffu, v, 4);
                v += __shfl_xor_sync(0xffffffffu, v, 2);
                v += __shfl_xor_sync(0xffffffffu, v, 1);
                if (l == 0) {
                    float y = v + blin;
                    out[step] = y;
                    g_y1 = y;
                    st_rel(&g_cy, step + 1);      // release orders g_y1
                }
            }
        }
    }
}

extern "C" void kernel_launch(void* const* d_in, const int* in_sizes, int n_in,
                              void* d_out, int out_size) {
    (void)in_sizes; (void)n_in; (void)out_size;
    const float* input = (const float*)d_in[0];
    const float* eh    = (const float*)d_in[1];
    const float* ec    = (const float*)d_in[2];
    const float* wih1  = (const float*)d_in[3];
    const float* whh1  = (const float*)d_in[4];
    const float* bih1  = (const float*)d_in[5];
    const float* bhh1  = (const float*)d_in[6];
    const float* wih2  = (const float*)d_in[7];
    const float* whh2  = (const float*)d_in[8];
    const float* bih2  = (const float*)d_in[9];
    const float* bhh2  = (const float*)d_in[10];
    const float* wlin  = (const float*)d_in[11];
    const float* blin  = (const float*)d_in[12];
    float* out = (float*)d_out;

    init_flags_kernel<<<1, 32>>>();
    lstm_decoder_kernel<<<3, NTHR>>>(input, eh, ec, wih1, whh1, bih1, bhh1,
                                     wih2, whh2, bih2, bhh2, wlin, blin, out);
}

// round 7
// speedup vs baseline: 2.7635x; 1.7730x over previous
#include <cuda_runtime.h>
#include <cooperative_groups.h>
#include <cstdint>

namespace cg = cooperative_groups;

#define H     100
#define G4    400
#define TSEQ  8192
#define FUT   1024
#define TOT   (TSEQ + FUT)
#define NSLOT 8
#define NTHR  448
#define CLU   4

// Communication block — identical static smem layout in every cluster CTA.
// h1ring lives in CTA1 (written by CTA0); pring lives in CTA2 (written by CTA1);
// ack1/cy/yv live in CTA0; ack2 lives in CTA1.
struct __align__(16) Comm {
    float h1ring[NSLOT][128];   // 4 KB
    float pring [NSLOT][400];   // 12.8 KB
    int   ch1;                  // in CTA1: h1 produced counter
    int   cp;                   // in CTA2: p produced counter
    int   ack1;                 // in CTA0: h1 consumed counter
    int   ack2;                 // in CTA1: p consumed counter
    int   cy;                   // in CTA0: y produced counter
    float yv;                   // in CTA0: fed-back y value
};

// ---- cluster-scope flag ops on GENERIC addresses (local smem or mapped peer smem) ----
static __device__ __forceinline__ int ld_acq(const int* p) {
    int v;
    asm volatile("ld.acquire.cluster.b32 %0, [%1];" : "=r"(v) : "l"(p) : "memory");
    return v;
}
static __device__ __forceinline__ void st_rel(int* p, int v) {
    asm volatile("st.release.cluster.b32 [%0], %1;" :: "l"(p), "r"(v) : "memory");
}
static __device__ __forceinline__ void fence_cluster() {
    asm volatile("fence.acq_rel.cluster;" ::: "memory");
}
static __device__ __forceinline__ void ffma2(unsigned long long& a, unsigned long long w, unsigned long long h) {
    asm("fma.rn.f32x2 %0, %1, %2, %3;" : "=l"(a) : "l"(w), "l"(h), "l"(a));
}
static __device__ __forceinline__ float f2lo(unsigned long long a) { return __uint_as_float((unsigned)a); }
static __device__ __forceinline__ float f2hi(unsigned long long a) { return __uint_as_float((unsigned)(a >> 32)); }
static __device__ __forceinline__ float sigm(float x)  { return __fdividef(1.0f, 1.0f + __expf(-x)); }
static __device__ __forceinline__ float tanh_(float x) { return __fdividef(2.0f, 1.0f + __expf(-2.0f * x)) - 1.0f; }

// 100-wide dot: 25 LDS.128 + 50 packed f32x2 FMAs against register weights.
static __device__ __forceinline__ float dot100(const unsigned long long* W, const float* sh) {
    const ulonglong2* h = (const ulonglong2*)sh;
    unsigned long long a0 = 0ull, a1 = 0ull;
#pragma unroll
    for (int j = 0; j < 25; j++) {
        ulonglong2 hv = h[j];
        ffma2(a0, W[2 * j],     hv.x);
        ffma2(a1, W[2 * j + 1], hv.y);
    }
    return f2lo(a0) + f2hi(a0) + f2lo(a1) + f2hi(a1);
}

__global__ void __launch_bounds__(NTHR, 1)
lstm_decoder_kernel(
    const float* __restrict__ input,
    const float* __restrict__ enc_h,
    const float* __restrict__ enc_c,
    const float* __restrict__ w_ih1,
    const float* __restrict__ w_hh1,
    const float* __restrict__ b_ih1,
    const float* __restrict__ b_hh1,
    const float* __restrict__ w_ih2,
    const float* __restrict__ w_hh2,
    const float* __restrict__ b_ih2,
    const float* __restrict__ b_hh2,
    const float* __restrict__ w_lin,
    const float* __restrict__ b_lin,
    float* __restrict__ out)
{
    cg::cluster_group cluster = cg::this_cluster();
    const unsigned rk = cluster.block_rank();

    __shared__ Comm cm;
    __shared__ __align__(16) float sx[TSEQ];   // CTA0 only: staged input
    __shared__ __align__(16) float shA[128];   // CTA0: h1 state; CTA2: h2 state
    __shared__ float sg[400];
    __shared__ float swl[112];
    __shared__ float syp[2][112];

    const int t = threadIdx.x;

    if (t == 0) { cm.ch1 = 0; cm.cp = 0; cm.ack1 = 0; cm.ack2 = 0; cm.cy = 0; cm.yv = 0.f; }
    cluster.sync();   // all flags initialized cluster-wide before any remote traffic

    if (rk == 0) {
        // ======================= CTA0: layer-1 LSTM =======================
        Comm* c1 = (Comm*)cluster.map_shared_rank(&cm, 1);
        unsigned long long Wr[50];
        float wi = 0.f, bb = 0.f, c1s = 0.f;
        if (t < G4) {
            const unsigned long long* wr = (const unsigned long long*)(w_hh1 + t * H);
#pragma unroll
            for (int j = 0; j < 50; j++) Wr[j] = wr[j];
            wi = w_ih1[t];
            bb = b_ih1[t] + b_hh1[t];
        }
        for (int i = t; i < TSEQ; i += NTHR) sx[i] = input[i];
        if (t < H) { shA[t] = enc_h[t]; c1s = enc_c[t]; }
        __syncthreads();

        for (int step = 0; step < TOT; ++step) {
            if (t < G4) {
                if (step >= NSLOT) {
                    while (ld_acq(&cm.ack1) < step - (NSLOT - 1)) {}
                }
                float x;
                if (step < TSEQ) x = sx[step];
                else {
                    while (ld_acq(&cm.cy) < step) {}
                    x = cm.yv;
                }
                float a = dot100(Wr, shA);
                sg[t] = fmaf(x, wi, a + bb);
            }
            __syncthreads();                                  // B1
            if (t < H) {
                float ig = sg[t], fg = sg[t + 100], gg = sg[t + 200], og = sg[t + 300];
                c1s = sigm(fg) * c1s + sigm(ig) * tanh_(gg);
                float hh = sigm(og) * tanh_(c1s);
                shA[t] = hh;
                c1->h1ring[step & (NSLOT - 1)][t] = hh;       // DSMEM write into CTA1
            }
            __syncthreads();                                  // B2
            if (t == 416) {
                fence_cluster();
                st_rel(&c1->ch1, step + 1);
            }
        }
    } else if (rk == 1) {
        // ======================= CTA1: p = W_ih2 @ h1 + b2 =======================
        Comm* c0 = (Comm*)cluster.map_shared_rank(&cm, 0);
        Comm* c2 = (Comm*)cluster.map_shared_rank(&cm, 2);
        unsigned long long Wr[50];
        float bb = 0.f;
        if (t < G4) {
            const unsigned long long* wr = (const unsigned long long*)(w_ih2 + t * H);
#pragma unroll
            for (int j = 0; j < 50; j++) Wr[j] = wr[j];
            bb = b_ih2[t] + b_hh2[t];
        }
        __syncthreads();

        for (int step = 0; step < TOT; ++step) {
            if (t < G4) {
                while (ld_acq(&cm.ch1) < step + 1) {}
                if (step >= NSLOT) {
                    while (ld_acq(&cm.ack2) < step - (NSLOT - 1)) {}
                }
                float a = dot100(Wr, cm.h1ring[step & (NSLOT - 1)]);
                c2->pring[step & (NSLOT - 1)][t] = a + bb;    // DSMEM write into CTA2
            }
            __syncthreads();                                  // single barrier/step
            if (t == 416) {
                fence_cluster();
                st_rel(&c2->cp, step + 1);
                st_rel(&c0->ack1, step + 1);
            }
        }
    } else if (rk == 2) {
        // ======================= CTA2: layer-2 recurrence + output =======================
        Comm* c0 = (Comm*)cluster.map_shared_rank(&cm, 0);
        Comm* c1 = (Comm*)cluster.map_shared_rank(&cm, 1);
        unsigned long long Wr[50];
        float c2s = 0.f;
        if (t < G4) {
            const unsigned long long* wr = (const unsigned long long*)(w_hh2 + t * H);
#pragma unroll
            for (int j = 0; j < 50; j++) Wr[j] = wr[j];
        }
        if (t < H) { shA[t] = 0.f; swl[t] = w_lin[t]; }
        const float blin = b_lin[0];
        __syncthreads();

        for (int step = 0; step < TOT; ++step) {
            if (t < G4) {
                while (ld_acq(&cm.cp) < step + 1) {}
                float q = dot100(Wr, shA);                    // W_hh2 @ h2(step-1)
                sg[t] = q + cm.pring[step & (NSLOT - 1)][t];
            }
            __syncthreads();                                  // B1 (p consumed)
            if (t == 400) {
                fence_cluster();
                st_rel(&c1->ack2, step + 1);
            }
            if (t < H) {
                float ig = sg[t], fg = sg[t + 100], gg = sg[t + 200], og = sg[t + 300];
                c2s = sigm(fg) * c2s + sigm(ig) * tanh_(gg);
                float hh = sigm(og) * tanh_(c2s);
                shA[t] = hh;
                syp[step & 1][t] = hh * swl[t];
            }
            __syncthreads();                                  // B2
            if (t >= 416) {
                int l = t - 416;
                float v = 0.f;
                if (l < 25) {
                    const float* sp = syp[step & 1];
                    int b4 = 4 * l;
                    v = sp[b4] + sp[b4 + 1] + sp[b4 + 2] + sp[b4 + 3];
                }
                v += __shfl_xor_sync(0xffffffffu, v, 16);
                v += __shfl_xor_sync(0xffffffffu, v, 8);
                v += __shfl_xor_sync(0xffffffffu, v, 4);
                v += __shfl_xor_sync(0xffffffffu, v, 2);
                v += __shfl_xor_sync(0xffffffffu, v, 1);
                if (l == 0) {
                    float y = v + blin;
                    out[step] = y;
                    if (step >= TSEQ - 1) {
                        c0->yv = y;                           // DSMEM write into CTA0
                        fence_cluster();
                        st_rel(&c0->cy, step + 1);
                    }
                }
            }
        }
    }
    // rk == 3: idle spacer CTA — participates in both cluster barriers only.

    cluster.sync();   // lifetime guard: no CTA exits while peers may still write its SMEM
}

extern "C" void kernel_launch(void* const* d_in, const int* in_sizes, int n_in,
                              void* d_out, int out_size) {
    (void)in_sizes; (void)n_in; (void)out_size;
    const float* input = (const float*)d_in[0];
    const float* eh    = (const float*)d_in[1];
    const float* ec    = (const float*)d_in[2];
    const float* wih1  = (const float*)d_in[3];
    const float* whh1  = (const float*)d_in[4];
    const float* bih1  = (const float*)d_in[5];
    const float* bhh1  = (const float*)d_in[6];
    const float* wih2  = (const float*)d_in[7];
    const float* whh2  = (const float*)d_in[8];
    const float* bih2  = (const float*)d_in[9];
    const float* bhh2  = (const float*)d_in[10];
    const float* wlin  = (const float*)d_in[11];
    const float* blin  = (const float*)d_in[12];
    float* out = (float*)d_out;

    cudaLaunchConfig_t cfg = {};
    cfg.gridDim  = dim3(CLU, 1, 1);
    cfg.blockDim = dim3(NTHR, 1, 1);
    cfg.dynamicSmemBytes = 0;
    cudaLaunchAttribute attrs[1];
    attrs[0].id = cudaLaunchAttributeClusterDimension;
    attrs[0].val.clusterDim.x = CLU;
    attrs[0].val.clusterDim.y = 1;
    attrs[0].val.clusterDim.z = 1;
    cfg.attrs = attrs;
    cfg.numAttrs = 1;

    cudaLaunchKernelEx(&cfg, lstm_decoder_kernel,
                       input, eh, ec, wih1, whh1, bih1, bhh1,
                       wih2, whh2, bih2, bhh2, wlin, blin, out);
}